// round 1
// baseline (speedup 1.0000x reference)
#include <cuda_runtime.h>
#include <math.h>

#define N_TOK 16384
#define MDIM  2048
#define PDIM  256
#define NEXP  64

#define BM 128
#define BN 128
#define BK 16
#define LDS_A (BM + 4)   // 132, pad to reduce store bank conflicts

// ---- scratch (static device globals: allocation-free) ----
__device__ float g_h[(size_t)N_TOK * PDIM];   // 16 MB, fits L2
__device__ float g_simn[PDIM * NEXP];         // column-normalized sim matrix [p][e]
__device__ float g_scale;

// ============================================================
// Prep: column-normalize sim_matrix (axis 0), compute logit scale
// ============================================================
__global__ void prep_kernel(const float* __restrict__ sim,
                            const float* __restrict__ temp)
{
    __shared__ float inv[NEXP];
    int tid = threadIdx.x;
    if (tid < NEXP) {
        float ss = 0.f;
        #pragma unroll 8
        for (int p = 0; p < PDIM; ++p) {
            float v = sim[p * NEXP + tid];
            ss += v * v;
        }
        inv[tid] = 1.0f / fmaxf(sqrtf(ss), 1e-12f);
    }
    if (tid == 0) {
        const float CLAMP_MAX = 4.605170185988091f;  // log(100)
        g_scale = expf(fminf(temp[0], CLAMP_MAX));
    }
    __syncthreads();
    for (int i = tid; i < PDIM * NEXP; i += blockDim.x)
        g_simn[i] = sim[i] * inv[i & (NEXP - 1)];
}

// ============================================================
// GEMM1: h[N,256] = x[N,2048] @ W[256,2048]^T + b
// 128x128x16 double-buffered fp32 SGEMM, 8x8 microtile, 256 threads
// ============================================================
__global__ __launch_bounds__(256, 2) void gemm_kernel(
    const float* __restrict__ A,   // x
    const float* __restrict__ B,   // W
    const float* __restrict__ bias)
{
    __shared__ __align__(16) float As[2][BK][LDS_A];
    __shared__ __align__(16) float Bs[2][BK][LDS_A];

    const int tid = threadIdx.x;
    const int tx = tid & 15;          // column group (8 cols each)
    const int ty = tid >> 4;          // row group (8 rows each)
    const int rowBase = blockIdx.x * BM;
    const int colBase = blockIdx.y * BN;

    const int lr0 = tid >> 2;         // 0..63  (loader row)
    const int lc  = (tid & 3) * 4;    // 0,4,8,12 (loader k-offset)

    const float* Ap = A + (size_t)(rowBase + lr0) * MDIM + lc;
    const float* Bp = B + (size_t)(colBase + lr0) * MDIM + lc;
    const size_t rstep = (size_t)64 * MDIM;

    // tile 0 -> buffer 0
    {
        float4 va0 = *(const float4*)(Ap);
        float4 va1 = *(const float4*)(Ap + rstep);
        float4 vb0 = *(const float4*)(Bp);
        float4 vb1 = *(const float4*)(Bp + rstep);
        As[0][lc+0][lr0] = va0.x; As[0][lc+1][lr0] = va0.y;
        As[0][lc+2][lr0] = va0.z; As[0][lc+3][lr0] = va0.w;
        As[0][lc+0][lr0+64] = va1.x; As[0][lc+1][lr0+64] = va1.y;
        As[0][lc+2][lr0+64] = va1.z; As[0][lc+3][lr0+64] = va1.w;
        Bs[0][lc+0][lr0] = vb0.x; Bs[0][lc+1][lr0] = vb0.y;
        Bs[0][lc+2][lr0] = vb0.z; Bs[0][lc+3][lr0] = vb0.w;
        Bs[0][lc+0][lr0+64] = vb1.x; Bs[0][lc+1][lr0+64] = vb1.y;
        Bs[0][lc+2][lr0+64] = vb1.z; Bs[0][lc+3][lr0+64] = vb1.w;
    }
    __syncthreads();

    float acc[8][8];
    #pragma unroll
    for (int i = 0; i < 8; ++i)
        #pragma unroll
        for (int j = 0; j < 8; ++j) acc[i][j] = 0.f;

    int buf = 0;
    const int NT = MDIM / BK;   // 128
    #pragma unroll 1
    for (int kt = 0; kt < NT; ++kt) {
        float4 pa0, pa1, pb0, pb1;
        const bool hasNext = (kt + 1) < NT;
        if (hasNext) {
            const float* Ap2 = Ap + (kt + 1) * BK;
            const float* Bp2 = Bp + (kt + 1) * BK;
            pa0 = *(const float4*)(Ap2);
            pa1 = *(const float4*)(Ap2 + rstep);
            pb0 = *(const float4*)(Bp2);
            pb1 = *(const float4*)(Bp2 + rstep);
        }
        #pragma unroll
        for (int k = 0; k < BK; ++k) {
            float4 a0 = *(const float4*)&As[buf][k][ty * 8];
            float4 a1 = *(const float4*)&As[buf][k][ty * 8 + 4];
            float4 b0 = *(const float4*)&Bs[buf][k][tx * 8];
            float4 b1 = *(const float4*)&Bs[buf][k][tx * 8 + 4];
            float af[8] = {a0.x, a0.y, a0.z, a0.w, a1.x, a1.y, a1.z, a1.w};
            float bf[8] = {b0.x, b0.y, b0.z, b0.w, b1.x, b1.y, b1.z, b1.w};
            #pragma unroll
            for (int i = 0; i < 8; ++i)
                #pragma unroll
                for (int j = 0; j < 8; ++j)
                    acc[i][j] += af[i] * bf[j];
        }
        if (hasNext) {
            const int nb = buf ^ 1;
            As[nb][lc+0][lr0] = pa0.x; As[nb][lc+1][lr0] = pa0.y;
            As[nb][lc+2][lr0] = pa0.z; As[nb][lc+3][lr0] = pa0.w;
            As[nb][lc+0][lr0+64] = pa1.x; As[nb][lc+1][lr0+64] = pa1.y;
            As[nb][lc+2][lr0+64] = pa1.z; As[nb][lc+3][lr0+64] = pa1.w;
            Bs[nb][lc+0][lr0] = pb0.x; Bs[nb][lc+1][lr0] = pb0.y;
            Bs[nb][lc+2][lr0] = pb0.z; Bs[nb][lc+3][lr0] = pb0.w;
            Bs[nb][lc+0][lr0+64] = pb1.x; Bs[nb][lc+1][lr0+64] = pb1.y;
            Bs[nb][lc+2][lr0+64] = pb1.z; Bs[nb][lc+3][lr0+64] = pb1.w;
            __syncthreads();
            buf = nb;
        }
    }

    // epilogue: + bias, store h
    float4 bv0 = *(const float4*)&bias[colBase + tx * 8];
    float4 bv1 = *(const float4*)&bias[colBase + tx * 8 + 4];
    #pragma unroll
    for (int i = 0; i < 8; ++i) {
        int row = rowBase + ty * 8 + i;
        float* cp = g_h + (size_t)row * PDIM + colBase + tx * 8;
        float4 o0 = make_float4(acc[i][0] + bv0.x, acc[i][1] + bv0.y,
                                acc[i][2] + bv0.z, acc[i][3] + bv0.w);
        float4 o1 = make_float4(acc[i][4] + bv1.x, acc[i][5] + bv1.y,
                                acc[i][6] + bv1.z, acc[i][7] + bv1.w);
        *(float4*)cp = o0;
        *(float4*)(cp + 4) = o1;
    }
}

// ============================================================
// Gate: per token -> L2-norm, logits (dot with g_simn), scale,
// mask, softmax, sort-free exact top-k count.
// One warp per token, 2 experts per lane (2*lane, 2*lane+1).
// ============================================================
#define WPC 8   // warps per CTA

__global__ __launch_bounds__(256) void gate_kernel(
    const float* __restrict__ mask,
    float* __restrict__ out_logits,
    float* __restrict__ out_topk)
{
    __shared__ float s_h[WPC][PDIM];
    __shared__ float s_sc[WPC][NEXP];

    const int tid  = threadIdx.x;
    const int w    = tid >> 5;
    const int lane = tid & 31;
    const int token = blockIdx.x * WPC + w;

    // load h row (256 floats), accumulate sumsq
    const float* hrow = g_h + (size_t)token * PDIM;
    float4 v0 = *(const float4*)(hrow + lane * 4);
    float4 v1 = *(const float4*)(hrow + (lane + 32) * 4);
    float ss = v0.x*v0.x + v0.y*v0.y + v0.z*v0.z + v0.w*v0.w
             + v1.x*v1.x + v1.y*v1.y + v1.z*v1.z + v1.w*v1.w;
    #pragma unroll
    for (int off = 16; off; off >>= 1)
        ss += __shfl_xor_sync(0xffffffffu, ss, off);
    const float invn = 1.0f / fmaxf(sqrtf(ss), 1e-12f);

    float* hw = s_h[w];
    *(float4*)(hw + lane * 4) = v0;
    *(float4*)(hw + (lane + 32) * 4) = v1;
    __syncwarp();

    // logits for experts e0 = 2*lane, e1 = 2*lane+1
    const int e0 = 2 * lane, e1 = 2 * lane + 1;
    float a0 = 0.f, a1 = 0.f;
    #pragma unroll 8
    for (int p = 0; p < PDIM; ++p) {
        float hv = hw[p];
        float2 sv = *(const float2*)&g_simn[p * NEXP + e0];
        a0 += hv * sv.x;
        a1 += hv * sv.y;
    }
    const float f = invn * g_scale;
    const float m0 = mask[e0], m1 = mask[e1];
    const float l0 = (m0 == 0.f) ? -1e9f : a0 * f;
    const float l1 = (m1 == 0.f) ? -1e9f : a1 * f;

    out_logits[(size_t)token * NEXP + e0] = l0;
    out_logits[(size_t)token * NEXP + e1] = l1;

    // softmax over 64 experts
    float mx = fmaxf(l0, l1);
    #pragma unroll
    for (int off = 16; off; off >>= 1)
        mx = fmaxf(mx, __shfl_xor_sync(0xffffffffu, mx, off));
    float x0 = expf(l0 - mx), x1 = expf(l1 - mx);
    float sum = x0 + x1;
    #pragma unroll
    for (int off = 16; off; off >>= 1)
        sum += __shfl_xor_sync(0xffffffffu, sum, off);
    const float inv_sum = 1.0f / sum;
    const float sA = x0 * inv_sum + 1e-14f;
    const float sB = x1 * inv_sum + 1e-14f;

    float* sw = s_sc[w];
    sw[e0] = sA;
    sw[e1] = sB;
    __syncwarp();

    // exact top-k without sorting:
    // G_e = sum of scores strictly ahead of e in a (any) stable descending
    // order; keep iff G_e < THRESHOLD. Prefix-sum multiset is tie-order
    // invariant, so this equals the reference's sort+cumsum count.
    float G0 = 0.f, G1 = 0.f;
    #pragma unroll
    for (int j = 0; j < NEXP; ++j) {
        float sj = sw[j];
        if ((sj > sA) || (sj == sA && j < e0)) G0 += sj;
        if ((sj > sB) || (sj == sB && j < e1)) G1 += sj;
    }
    int cnt = (G0 < 1.0f ? 1 : 0) + (G1 < 1.0f ? 1 : 0);
    float msum = m0 + m1;
    #pragma unroll
    for (int off = 16; off; off >>= 1) {
        cnt  += __shfl_xor_sync(0xffffffffu, cnt, off);
        msum += __shfl_xor_sync(0xffffffffu, msum, off);
    }
    if (lane == 0 && out_topk) {
        int active = (int)rintf(msum);
        out_topk[token] = (float)min(cnt, active);
    }
}

// ============================================================
extern "C" void kernel_launch(void* const* d_in, const int* in_sizes, int n_in,
                              void* d_out, int out_size)
{
    const float* x    = (const float*)d_in[0];
    const float* W    = (const float*)d_in[1];
    const float* b    = (const float*)d_in[2];
    const float* sim  = (const float*)d_in[3];
    const float* temp = (const float*)d_in[4];
    const float* mask = (const float*)d_in[5];

    float* out = (float*)d_out;
    float* out_topk = (out_size >= N_TOK * NEXP + N_TOK)
                          ? out + (size_t)N_TOK * NEXP : nullptr;

    prep_kernel<<<1, 256>>>(sim, temp);
    gemm_kernel<<<dim3(N_TOK / BM, PDIM / BN), 256>>>(x, W, b);
    gate_kernel<<<N_TOK / WPC, 256>>>(mask, out, out_topk);
}

// round 3
// speedup vs baseline: 1.9074x; 1.9074x over previous
#include <cuda_runtime.h>
#include <cuda_bf16.h>
#include <math.h>
#include <stdint.h>

#define N_TOK 16384
#define MDIM  2048
#define PDIM  256
#define NEXP  64

#define BM   128
#define BN   128
#define BK   64
#define NKC  (MDIM/BK)     // 32 k-chunks
#define NMB  (N_TOK/BM)    // 128 m-blocks

#define A_TILE_B  (BM*BK*2)        // 16384 B
#define B_HALF_B  (BN*BK*2)        // 16384 B (this CTA's half of W rows)
#define B_FULL_B  (PDIM*BK*2)      // 32768 B
#define STAGE_B   (2*A_TILE_B + 2*B_HALF_B)   // 65536
#define SMEM_TOTAL (2*STAGE_B)                // 131072

// ---- static device scratch (allocation-free) ----
__device__ uint4 g_xhi[(size_t)N_TOK*MDIM*2/16];   // 64 MB, tiled+swizzled bf16
__device__ uint4 g_xlo[(size_t)N_TOK*MDIM*2/16];   // 64 MB
__device__ uint4 g_whi[(size_t)PDIM*MDIM*2/16];    // 1 MB
__device__ uint4 g_wlo[(size_t)PDIM*MDIM*2/16];    // 1 MB
__device__ float g_h[(size_t)N_TOK * PDIM];        // 16 MB
__device__ float g_simn[PDIM * NEXP];
__device__ float g_scale;

// ============================================================
// helpers
// ============================================================
static __device__ __forceinline__ uint32_t smem_u32(const void* p) {
    uint32_t a;
    asm("{ .reg .u64 t; cvta.to.shared.u64 t, %1; cvt.u32.u64 %0, t; }"
        : "=r"(a) : "l"(p));
    return a;
}

#define CP16(dst, src) \
    asm volatile("cp.async.cg.shared.global [%0], [%1], 16;" :: "r"(dst), "l"(src))
#define CPCOMMIT() asm volatile("cp.async.commit_group;" ::: "memory")
#define CPWAIT1()  asm volatile("cp.async.wait_group 1;"  ::: "memory")
#define CPWAIT0()  asm volatile("cp.async.wait_group 0;"  ::: "memory")

#define LDSM4(r, addr) \
    asm volatile("ldmatrix.sync.aligned.m8n8.x4.shared.b16 {%0,%1,%2,%3}, [%4];" \
        : "=r"((r)[0]), "=r"((r)[1]), "=r"((r)[2]), "=r"((r)[3]) : "r"(addr))

#define MMA16816(d, a, b) \
    asm volatile("mma.sync.aligned.m16n8k16.row.col.f32.bf16.bf16.f32 " \
        "{%0,%1,%2,%3}, {%4,%5,%6,%7}, {%8,%9}, {%0,%1,%2,%3};" \
        : "+f"((d)[0]), "+f"((d)[1]), "+f"((d)[2]), "+f"((d)[3]) \
        : "r"((a)[0]), "r"((a)[1]), "r"((a)[2]), "r"((a)[3]), \
          "r"((b)[0]), "r"((b)[1]))

// ============================================================
// prep_sim: column-normalize sim_matrix, compute logit scale
// ============================================================
__global__ void prep_sim_kernel(const float* __restrict__ sim,
                                const float* __restrict__ temp)
{
    __shared__ float ss[NEXP];
    __shared__ float inv[NEXP];
    int t = threadIdx.x;
    if (t < NEXP) ss[t] = 0.f;
    __syncthreads();
    for (int i = t * 4; i < PDIM * NEXP; i += 4096) {
        float4 v = *(const float4*)(sim + i);
        atomicAdd(&ss[(i + 0) & 63], v.x * v.x);
        atomicAdd(&ss[(i + 1) & 63], v.y * v.y);
        atomicAdd(&ss[(i + 2) & 63], v.z * v.z);
        atomicAdd(&ss[(i + 3) & 63], v.w * v.w);
    }
    __syncthreads();
    if (t < NEXP) inv[t] = 1.0f / fmaxf(sqrtf(ss[t]), 1e-12f);
    if (t == 0)  g_scale = expf(fminf(temp[0], 4.605170185988091f));
    __syncthreads();
    for (int i = t * 4; i < PDIM * NEXP; i += 4096) {
        float4 v = *(const float4*)(sim + i);
        v.x *= inv[(i + 0) & 63];
        v.y *= inv[(i + 1) & 63];
        v.z *= inv[(i + 2) & 63];
        v.w *= inv[(i + 3) & 63];
        *(float4*)(g_simn + i) = v;
    }
}

// ============================================================
// bf16 hi/lo split + SW128-swizzled tiled store
// ============================================================
static __device__ __forceinline__ void split8_store(
    const float* __restrict__ src, uint4* dst_hi, uint4* dst_lo, uint32_t byte_off)
{
    float4 v0 = *(const float4*)(src);
    float4 v1 = *(const float4*)(src + 4);
    float vs[8] = {v0.x, v0.y, v0.z, v0.w, v1.x, v1.y, v1.z, v1.w};
    union { uint4 q; __nv_bfloat16 b[8]; } H, L;
    #pragma unroll
    for (int i = 0; i < 8; ++i) {
        __nv_bfloat16 h = __float2bfloat16(vs[i]);
        H.b[i] = h;
        L.b[i] = __float2bfloat16(vs[i] - __bfloat162float(h));
    }
    uint32_t sw = byte_off ^ ((byte_off >> 3) & 0x70);
    *(uint4*)((unsigned char*)dst_hi + sw) = H.q;
    *(uint4*)((unsigned char*)dst_lo + sw) = L.q;
}

// x -> tiles [mb][kc][128 rows][64 bf16 swizzled]
__global__ __launch_bounds__(256) void convert_x_kernel(const float* __restrict__ x)
{
    const int mb = blockIdx.x, kc = blockIdx.y, t = threadIdx.x;
    uint4* dh = g_xhi + (size_t)(mb * NKC + kc) * (A_TILE_B / 16);
    uint4* dl = g_xlo + (size_t)(mb * NKC + kc) * (A_TILE_B / 16);
    #pragma unroll
    for (int u = t; u < BM * 8; u += 256) {
        int row = u >> 3, cu = u & 7;
        const float* src = x + (size_t)(mb * BM + row) * MDIM + kc * BK + cu * 8;
        split8_store(src, dh, dl, row * 128 + cu * 16);
    }
}

// W -> tiles [kc][256 rows][64 bf16 swizzled]
__global__ __launch_bounds__(256) void convert_w_kernel(const float* __restrict__ W)
{
    const int kc = blockIdx.x, t = threadIdx.x;
    uint4* dh = g_whi + (size_t)kc * (B_FULL_B / 16);
    uint4* dl = g_wlo + (size_t)kc * (B_FULL_B / 16);
    #pragma unroll
    for (int u = t; u < PDIM * 8; u += 256) {
        int row = u >> 3, cu = u & 7;
        const float* src = W + (size_t)row * MDIM + kc * BK + cu * 8;
        split8_store(src, dh, dl, row * 128 + cu * 16);
    }
}

// ============================================================
// HMMA GEMM: h = x @ W^T + b  (bf16 hi/lo 3-product split, fp32 acc)
// CTA: 128x128x64, 8 warps (2M x 4N), warp tile 64x32
// ============================================================
static __device__ __forceinline__ void load_stage(uint32_t sbase, int mb, int by, int kt)
{
    const int t = threadIdx.x;
    const uint4* ah = g_xhi + (size_t)(mb * NKC + kt) * (A_TILE_B / 16);
    const uint4* al = g_xlo + (size_t)(mb * NKC + kt) * (A_TILE_B / 16);
    const uint4* bh = g_whi + (size_t)kt * (B_FULL_B / 16) + by * (B_HALF_B / 16);
    const uint4* bl = g_wlo + (size_t)kt * (B_FULL_B / 16) + by * (B_HALF_B / 16);
    #pragma unroll
    for (int i = 0; i < 4; ++i) {
        int idx = t + i * 256;
        CP16(sbase + idx * 16,                              (const void*)(ah + idx));
        CP16(sbase + A_TILE_B + idx * 16,                   (const void*)(al + idx));
        CP16(sbase + 2 * A_TILE_B + idx * 16,               (const void*)(bh + idx));
        CP16(sbase + 2 * A_TILE_B + B_HALF_B + idx * 16,    (const void*)(bl + idx));
    }
}

__global__ __launch_bounds__(256, 1) void gemm2_kernel(const float* __restrict__ bias)
{
    extern __shared__ __align__(1024) unsigned char smem[];
    const uint32_t sb0 = smem_u32(smem);
    const int tid = threadIdx.x, wid = tid >> 5, lane = tid & 31;
    const int mb = blockIdx.x, by = blockIdx.y;
    const int wm = wid & 1;        // 0..1 (M)
    const int wn = wid >> 1;       // 0..3 (N)

    // prologue
    load_stage(sb0, mb, by, 0); CPCOMMIT();
    load_stage(sb0 + STAGE_B, mb, by, 1); CPCOMMIT();

    // per-lane ldmatrix address precompute
    // A: lanes 0-7 m0-7/klo, 8-15 m8-15/klo, 16-23 m0-7/khi, 24-31 m8-15/khi
    const int rA = lane & 15;
    const uint32_t aHalf = (uint32_t)(lane >> 4) * 16;
    const uint32_t xorA = (uint32_t)(rA & 7) << 4;
    uint32_t aRow[4];
    #pragma unroll
    for (int mf = 0; mf < 4; ++mf)
        aRow[mf] = (uint32_t)(wm * 64 + mf * 16 + rA) * 128;

    // B: lanes 0-7 n0-7/klo, 8-15 n0-7/khi, 16-23 n8-15/klo, 24-31 n8-15/khi
    const int nR = wn * 32 + ((lane >> 4) & 1) * 8 + (lane & 7);
    const uint32_t bHalf = (uint32_t)((lane >> 3) & 1) * 16;
    const uint32_t xorB = (uint32_t)(lane & 7) << 4;
    uint32_t bRow[2];
    bRow[0] = (uint32_t)nR * 128;
    bRow[1] = (uint32_t)(nR + 16) * 128;

    float acc[4][4][4];
    #pragma unroll
    for (int mf = 0; mf < 4; ++mf)
        #pragma unroll
        for (int nf = 0; nf < 4; ++nf)
            #pragma unroll
            for (int i = 0; i < 4; ++i) acc[mf][nf][i] = 0.f;

    for (int kt = 0; kt < NKC; ++kt) {
        const uint32_t sbase = sb0 + (kt & 1) * STAGE_B;
        if (kt == NKC - 1) { CPWAIT0(); } else { CPWAIT1(); }
        __syncthreads();

        const uint32_t aBaseH = sbase;
        const uint32_t aBaseL = sbase + A_TILE_B;
        const uint32_t bBaseH = sbase + 2 * A_TILE_B;
        const uint32_t bBaseL = sbase + 2 * A_TILE_B + B_HALF_B;

        #pragma unroll
        for (int ks = 0; ks < 4; ++ks) {
            const uint32_t kb = (uint32_t)ks * 32;
            const uint32_t aOff = (kb + aHalf) ^ xorA;
            const uint32_t bOff = (kb + bHalf) ^ xorB;

            uint32_t aH[4][4], aL[4][4], bH[4][2], bL[4][2];
            #pragma unroll
            for (int mf = 0; mf < 4; ++mf)
                LDSM4(aH[mf], aBaseH + aRow[mf] + aOff);
            #pragma unroll
            for (int nf2 = 0; nf2 < 2; ++nf2) {
                uint32_t r[4];
                LDSM4(r, bBaseH + bRow[nf2] + bOff);
                bH[2*nf2][0] = r[0]; bH[2*nf2][1] = r[1];
                bH[2*nf2+1][0] = r[2]; bH[2*nf2+1][1] = r[3];
            }
            #pragma unroll
            for (int mf = 0; mf < 4; ++mf)
                #pragma unroll
                for (int nf = 0; nf < 4; ++nf)
                    MMA16816(acc[mf][nf], aH[mf], bH[nf]);

            #pragma unroll
            for (int nf2 = 0; nf2 < 2; ++nf2) {
                uint32_t r[4];
                LDSM4(r, bBaseL + bRow[nf2] + bOff);
                bL[2*nf2][0] = r[0]; bL[2*nf2][1] = r[1];
                bL[2*nf2+1][0] = r[2]; bL[2*nf2+1][1] = r[3];
            }
            #pragma unroll
            for (int mf = 0; mf < 4; ++mf)
                #pragma unroll
                for (int nf = 0; nf < 4; ++nf)
                    MMA16816(acc[mf][nf], aH[mf], bL[nf]);

            #pragma unroll
            for (int mf = 0; mf < 4; ++mf)
                LDSM4(aL[mf], aBaseL + aRow[mf] + aOff);
            #pragma unroll
            for (int mf = 0; mf < 4; ++mf)
                #pragma unroll
                for (int nf = 0; nf < 4; ++nf)
                    MMA16816(acc[mf][nf], aL[mf], bH[nf]);
        }
        __syncthreads();
        if (kt + 2 < NKC) {
            load_stage(sbase, mb, by, kt + 2); CPCOMMIT();
        }
    }

    // epilogue: acc -> g_h (+bias), direct float2 stores
    const int colB = by * BN + wn * 32 + (lane & 3) * 2;
    const int rowB = mb * BM + wm * 64 + (lane >> 2);
    #pragma unroll
    for (int nf = 0; nf < 4; ++nf) {
        const int col = colB + nf * 8;
        float2 bv = *(const float2*)(bias + col);
        #pragma unroll
        for (int mf = 0; mf < 4; ++mf) {
            const int r0 = rowB + mf * 16;
            float2 v0 = make_float2(acc[mf][nf][0] + bv.x, acc[mf][nf][1] + bv.y);
            float2 v1 = make_float2(acc[mf][nf][2] + bv.x, acc[mf][nf][3] + bv.y);
            *(float2*)(g_h + (size_t)r0 * PDIM + col)       = v0;
            *(float2*)(g_h + (size_t)(r0 + 8) * PDIM + col) = v1;
        }
    }
}

// ============================================================
// Gate: L2-norm, logits, softmax, sort-free exact top-k (1 warp/token)
// ============================================================
#define WPC 8

__global__ __launch_bounds__(256) void gate_kernel(
    const float* __restrict__ mask,
    float* __restrict__ out_logits,
    float* __restrict__ out_topk)
{
    __shared__ float s_h[WPC][PDIM];
    __shared__ float s_sc[WPC][NEXP];

    const int tid  = threadIdx.x;
    const int w    = tid >> 5;
    const int lane = tid & 31;
    const int token = blockIdx.x * WPC + w;

    const float* hrow = g_h + (size_t)token * PDIM;
    float4 v0 = *(const float4*)(hrow + lane * 4);
    float4 v1 = *(const float4*)(hrow + (lane + 32) * 4);
    float ss = v0.x*v0.x + v0.y*v0.y + v0.z*v0.z + v0.w*v0.w
             + v1.x*v1.x + v1.y*v1.y + v1.z*v1.z + v1.w*v1.w;
    #pragma unroll
    for (int off = 16; off; off >>= 1)
        ss += __shfl_xor_sync(0xffffffffu, ss, off);
    const float invn = 1.0f / fmaxf(sqrtf(ss), 1e-12f);

    float* hw = s_h[w];
    *(float4*)(hw + lane * 4) = v0;
    *(float4*)(hw + (lane + 32) * 4) = v1;
    __syncwarp();

    const int e0 = 2 * lane, e1 = 2 * lane + 1;
    float a0 = 0.f, a1 = 0.f;
    #pragma unroll 8
    for (int p = 0; p < PDIM; ++p) {
        float hv = hw[p];
        float2 sv = *(const float2*)&g_simn[p * NEXP + e0];
        a0 += hv * sv.x;
        a1 += hv * sv.y;
    }
    const float f = invn * g_scale;
    const float m0 = mask[e0], m1 = mask[e1];
    const float l0 = (m0 == 0.f) ? -1e9f : a0 * f;
    const float l1 = (m1 == 0.f) ? -1e9f : a1 * f;

    out_logits[(size_t)token * NEXP + e0] = l0;
    out_logits[(size_t)token * NEXP + e1] = l1;

    float mx = fmaxf(l0, l1);
    #pragma unroll
    for (int off = 16; off; off >>= 1)
        mx = fmaxf(mx, __shfl_xor_sync(0xffffffffu, mx, off));
    float x0 = expf(l0 - mx), x1 = expf(l1 - mx);
    float sum = x0 + x1;
    #pragma unroll
    for (int off = 16; off; off >>= 1)
        sum += __shfl_xor_sync(0xffffffffu, sum, off);
    const float inv_sum = 1.0f / sum;
    const float sA = x0 * inv_sum + 1e-14f;
    const float sB = x1 * inv_sum + 1e-14f;

    float* sw = s_sc[w];
    sw[e0] = sA;
    sw[e1] = sB;
    __syncwarp();

    float G0 = 0.f, G1 = 0.f;
    #pragma unroll
    for (int j = 0; j < NEXP; ++j) {
        float sj = sw[j];
        if ((sj > sA) || (sj == sA && j < e0)) G0 += sj;
        if ((sj > sB) || (sj == sB && j < e1)) G1 += sj;
    }
    int cnt = (G0 < 1.0f ? 1 : 0) + (G1 < 1.0f ? 1 : 0);
    float msum = m0 + m1;
    #pragma unroll
    for (int off = 16; off; off >>= 1) {
        cnt  += __shfl_xor_sync(0xffffffffu, cnt, off);
        msum += __shfl_xor_sync(0xffffffffu, msum, off);
    }
    if (lane == 0 && out_topk) {
        int active = (int)rintf(msum);
        out_topk[token] = (float)min(cnt, active);
    }
}

// ============================================================
extern "C" void kernel_launch(void* const* d_in, const int* in_sizes, int n_in,
                              void* d_out, int out_size)
{
    const float* x    = (const float*)d_in[0];
    const float* W    = (const float*)d_in[1];
    const float* b    = (const float*)d_in[2];
    const float* sim  = (const float*)d_in[3];
    const float* temp = (const float*)d_in[4];
    const float* mask = (const float*)d_in[5];

    float* out = (float*)d_out;
    float* out_topk = (out_size >= N_TOK * NEXP + N_TOK)
                          ? out + (size_t)N_TOK * NEXP : nullptr;

    static int smem_set = 0;
    if (!smem_set) {
        cudaFuncSetAttribute(gemm2_kernel,
                             cudaFuncAttributeMaxDynamicSharedMemorySize, SMEM_TOTAL);
        smem_set = 1;
    }

    prep_sim_kernel<<<1, 1024>>>(sim, temp);
    convert_w_kernel<<<NKC, 256>>>(W);
    convert_x_kernel<<<dim3(NMB, NKC), 256>>>(x);
    gemm2_kernel<<<dim3(NMB, 2), 256, SMEM_TOTAL>>>(b);
    gate_kernel<<<N_TOK / WPC, 256>>>(mask, out, out_topk);
}

// round 4
// speedup vs baseline: 2.0345x; 1.0667x over previous
#include <cuda_runtime.h>
#include <cuda_bf16.h>
#include <math.h>
#include <stdint.h>

#define N_TOK 16384
#define MDIM  2048
#define PDIM  256
#define NEXP  64

#define BM   128
#define BN   256
#define BK   64
#define NKC  (MDIM/BK)     // 32 k-chunks
#define NMB  (N_TOK/BM)    // 128 m-blocks

#define A_TILE_B  (BM*BK*2)        // 16384 B (one of hi/lo)
#define B_TILE_B  (BN*BK*2)        // 32768 B (one of hi/lo, full 256 rows)
#define STAGE_B   (2*A_TILE_B + 2*B_TILE_B)   // 98304 B
// epilogue overlay offsets (within the 2*STAGE_B = 196608 B arena)
#define HBF_HI_OFF 0         // [4 kc][128 rows][128B]  = 65536
#define HBF_LO_OFF 65536
#define SN_HI_OFF  131072    // [4 kc][64 rows][128B]   = 32768
#define SN_LO_OFF  163840
#define HDR_OFF    196608    // s_ss/s_inv 512B, s_sc 2048B
#define SMEM_TOTAL (196608 + 512 + 2048)   // 199168

// ---- static device scratch (allocation-free) ----
__device__ uint4 g_xhi[(size_t)N_TOK*MDIM*2/16];   // 64 MB tiled+swizzled bf16
__device__ uint4 g_xlo[(size_t)N_TOK*MDIM*2/16];   // 64 MB
__device__ uint4 g_whi[(size_t)PDIM*MDIM*2/16];    // 1 MB
__device__ uint4 g_wlo[(size_t)PDIM*MDIM*2/16];    // 1 MB
__device__ uint4 g_snhi[2048];                     // 32 KB: simn^T bf16 hi, swizzled
__device__ uint4 g_snlo[2048];                     // 32 KB
__device__ float g_scale;

// ============================================================
// helpers
// ============================================================
static __device__ __forceinline__ uint32_t smem_u32(const void* p) {
    uint32_t a;
    asm("{ .reg .u64 t; cvta.to.shared.u64 t, %1; cvt.u32.u64 %0, t; }"
        : "=r"(a) : "l"(p));
    return a;
}

#define CP16(dst, src) \
    asm volatile("cp.async.cg.shared.global [%0], [%1], 16;" :: "r"(dst), "l"(src))
#define CPCOMMIT() asm volatile("cp.async.commit_group;" ::: "memory")
#define CPWAIT1()  asm volatile("cp.async.wait_group 1;"  ::: "memory")
#define CPWAIT0()  asm volatile("cp.async.wait_group 0;"  ::: "memory")

#define LDSM4(r, addr) \
    asm volatile("ldmatrix.sync.aligned.m8n8.x4.shared.b16 {%0,%1,%2,%3}, [%4];" \
        : "=r"((r)[0]), "=r"((r)[1]), "=r"((r)[2]), "=r"((r)[3]) : "r"(addr))

#define MMA16816(d, a, b) \
    asm volatile("mma.sync.aligned.m16n8k16.row.col.f32.bf16.bf16.f32 " \
        "{%0,%1,%2,%3}, {%4,%5,%6,%7}, {%8,%9}, {%0,%1,%2,%3};" \
        : "+f"((d)[0]), "+f"((d)[1]), "+f"((d)[2]), "+f"((d)[3]) \
        : "r"((a)[0]), "r"((a)[1]), "r"((a)[2]), "r"((a)[3]), \
          "r"((b)[0]), "r"((b)[1]))

static __device__ __forceinline__ uint32_t sw128(uint32_t o) {
    return o ^ ((o >> 3) & 0x70);
}

// ============================================================
// prep_sim: column-normalize sim_matrix -> transposed bf16 hi/lo
// swizzled tiles [kc4][64 experts][64k]; compute logit scale
// ============================================================
__global__ void prep_sim_kernel(const float* __restrict__ sim,
                                const float* __restrict__ temp)
{
    __shared__ float inv[NEXP];
    int t = threadIdx.x;
    if (t < NEXP) {
        float ss = 0.f;
        #pragma unroll 8
        for (int p = 0; p < PDIM; ++p) {
            float v = sim[p * NEXP + t];
            ss += v * v;
        }
        inv[t] = 1.0f / fmaxf(sqrtf(ss), 1e-12f);
    }
    if (t == 0) g_scale = expf(fminf(temp[0], 4.605170185988091f));
    __syncthreads();
    __nv_bfloat16* sh = (__nv_bfloat16*)g_snhi;
    __nv_bfloat16* sl = (__nv_bfloat16*)g_snlo;
    for (int idx = t; idx < NEXP * PDIM; idx += 1024) {
        int e = idx >> 8, p = idx & 255;
        float v = sim[p * NEXP + e] * inv[e];
        __nv_bfloat16 h = __float2bfloat16(v);
        __nv_bfloat16 l = __float2bfloat16(v - __bfloat162float(h));
        uint32_t off = (uint32_t)(p >> 6) * 8192 + sw128((uint32_t)e * 128 + (p & 63) * 2);
        *(__nv_bfloat16*)((char*)sh + off) = h;
        *(__nv_bfloat16*)((char*)sl + off) = l;
    }
}

// ============================================================
// bf16 hi/lo split + SW128-swizzled tiled store
// ============================================================
static __device__ __forceinline__ void split8_store(
    const float* __restrict__ src, uint4* dst_hi, uint4* dst_lo, uint32_t byte_off)
{
    float4 v0 = *(const float4*)(src);
    float4 v1 = *(const float4*)(src + 4);
    float vs[8] = {v0.x, v0.y, v0.z, v0.w, v1.x, v1.y, v1.z, v1.w};
    union { uint4 q; __nv_bfloat16 b[8]; } H, L;
    #pragma unroll
    for (int i = 0; i < 8; ++i) {
        __nv_bfloat16 h = __float2bfloat16(vs[i]);
        H.b[i] = h;
        L.b[i] = __float2bfloat16(vs[i] - __bfloat162float(h));
    }
    uint32_t sw = sw128(byte_off);
    *(uint4*)((unsigned char*)dst_hi + sw) = H.q;
    *(uint4*)((unsigned char*)dst_lo + sw) = L.q;
}

__global__ __launch_bounds__(256) void convert_x_kernel(const float* __restrict__ x)
{
    const int mb = blockIdx.x, kc = blockIdx.y, t = threadIdx.x;
    uint4* dh = g_xhi + (size_t)(mb * NKC + kc) * (A_TILE_B / 16);
    uint4* dl = g_xlo + (size_t)(mb * NKC + kc) * (A_TILE_B / 16);
    #pragma unroll
    for (int u = t; u < BM * 8; u += 256) {
        int row = u >> 3, cu = u & 7;
        const float* src = x + (size_t)(mb * BM + row) * MDIM + kc * BK + cu * 8;
        split8_store(src, dh, dl, row * 128 + cu * 16);
    }
}

__global__ __launch_bounds__(256) void convert_w_kernel(const float* __restrict__ W)
{
    const int kc = blockIdx.x, t = threadIdx.x;
    uint4* dh = g_whi + (size_t)kc * (B_TILE_B / 16);
    uint4* dl = g_wlo + (size_t)kc * (B_TILE_B / 16);
    #pragma unroll
    for (int u = t; u < PDIM * 8; u += 256) {
        int row = u >> 3, cu = u & 7;
        const float* src = W + (size_t)row * MDIM + kc * BK + cu * 8;
        split8_store(src, dh, dl, row * 128 + cu * 16);
    }
}

// ============================================================
// Fused GEMM + gate kernel
// CTA 128x256x64, 8 warps (2M x 4N), warp tile 64x64
// ============================================================
static __device__ __forceinline__ void load_stage(uint32_t sbase, int mb, int kt)
{
    const int t = threadIdx.x;
    const uint4* ah = g_xhi + (size_t)(mb * NKC + kt) * (A_TILE_B / 16);
    const uint4* al = g_xlo + (size_t)(mb * NKC + kt) * (A_TILE_B / 16);
    const uint4* bh = g_whi + (size_t)kt * (B_TILE_B / 16);
    const uint4* bl = g_wlo + (size_t)kt * (B_TILE_B / 16);
    #pragma unroll
    for (int i = 0; i < 4; ++i) {
        int idx = t + i * 256;
        CP16(sbase + idx * 16,              (const void*)(ah + idx));
        CP16(sbase + A_TILE_B + idx * 16,   (const void*)(al + idx));
    }
    #pragma unroll
    for (int i = 0; i < 8; ++i) {
        int idx = t + i * 256;
        CP16(sbase + 2 * A_TILE_B + idx * 16,              (const void*)(bh + idx));
        CP16(sbase + 2 * A_TILE_B + B_TILE_B + idx * 16,   (const void*)(bl + idx));
    }
}

__global__ __launch_bounds__(256, 1) void gemm_gate_kernel(
    const float* __restrict__ bias,
    const float* __restrict__ mask,
    float* __restrict__ out_logits,
    float* __restrict__ out_topk)
{
    extern __shared__ __align__(1024) unsigned char smem[];
    const uint32_t sb0 = smem_u32(smem);
    const int tid = threadIdx.x, wid = tid >> 5, lane = tid & 31;
    const int mb = blockIdx.x;
    const int wm = wid & 1;        // 0..1 (M, 64 rows each)
    const int wn = wid >> 1;       // 0..3 (N, 64 cols each)

    load_stage(sb0, mb, 0); CPCOMMIT();
    load_stage(sb0 + STAGE_B, mb, 1); CPCOMMIT();

    const int rA = lane & 15;
    const uint32_t aHalf = (uint32_t)(lane >> 4) * 16;
    const uint32_t xorA = (uint32_t)(rA & 7) << 4;
    uint32_t aRow[4];
    #pragma unroll
    for (int mf = 0; mf < 4; ++mf)
        aRow[mf] = (uint32_t)(wm * 64 + mf * 16 + rA) * 128;

    const uint32_t bHalf = (uint32_t)((lane >> 3) & 1) * 16;
    const uint32_t xorB = (uint32_t)(lane & 7) << 4;
    uint32_t bRow[4];
    #pragma unroll
    for (int nf2 = 0; nf2 < 4; ++nf2)
        bRow[nf2] = (uint32_t)(wn * 64 + nf2 * 16 + ((lane >> 4) & 1) * 8 + (lane & 7)) * 128;

    float acc[4][8][4];
    #pragma unroll
    for (int mf = 0; mf < 4; ++mf)
        #pragma unroll
        for (int nf = 0; nf < 8; ++nf)
            #pragma unroll
            for (int i = 0; i < 4; ++i) acc[mf][nf][i] = 0.f;

    for (int kt = 0; kt < NKC; ++kt) {
        const uint32_t sbase = sb0 + (kt & 1) * STAGE_B;
        if (kt == NKC - 1) { CPWAIT0(); } else { CPWAIT1(); }
        __syncthreads();

        const uint32_t aBaseH = sbase;
        const uint32_t aBaseL = sbase + A_TILE_B;
        const uint32_t bBaseH = sbase + 2 * A_TILE_B;
        const uint32_t bBaseL = sbase + 2 * A_TILE_B + B_TILE_B;

        #pragma unroll
        for (int ks = 0; ks < 4; ++ks) {
            const uint32_t kb = (uint32_t)ks * 32;
            const uint32_t aOff = (kb + aHalf) ^ xorA;
            const uint32_t bOff = (kb + bHalf) ^ xorB;

            uint32_t aH[4][4], bH[8][2];
            #pragma unroll
            for (int mf = 0; mf < 4; ++mf)
                LDSM4(aH[mf], aBaseH + aRow[mf] + aOff);
            #pragma unroll
            for (int nf2 = 0; nf2 < 4; ++nf2) {
                uint32_t r[4];
                LDSM4(r, bBaseH + bRow[nf2] + bOff);
                bH[2*nf2][0] = r[0]; bH[2*nf2][1] = r[1];
                bH[2*nf2+1][0] = r[2]; bH[2*nf2+1][1] = r[3];
            }
            #pragma unroll
            for (int mf = 0; mf < 4; ++mf)
                #pragma unroll
                for (int nf = 0; nf < 8; ++nf)
                    MMA16816(acc[mf][nf], aH[mf], bH[nf]);

            {
                uint32_t bL[8][2];
                #pragma unroll
                for (int nf2 = 0; nf2 < 4; ++nf2) {
                    uint32_t r[4];
                    LDSM4(r, bBaseL + bRow[nf2] + bOff);
                    bL[2*nf2][0] = r[0]; bL[2*nf2][1] = r[1];
                    bL[2*nf2+1][0] = r[2]; bL[2*nf2+1][1] = r[3];
                }
                #pragma unroll
                for (int mf = 0; mf < 4; ++mf)
                    #pragma unroll
                    for (int nf = 0; nf < 8; ++nf)
                        MMA16816(acc[mf][nf], aH[mf], bL[nf]);
            }
            {
                uint32_t aL[4][4];
                #pragma unroll
                for (int mf = 0; mf < 4; ++mf)
                    LDSM4(aL[mf], aBaseL + aRow[mf] + aOff);
                #pragma unroll
                for (int mf = 0; mf < 4; ++mf)
                    #pragma unroll
                    for (int nf = 0; nf < 8; ++nf)
                        MMA16816(acc[mf][nf], aL[mf], bH[nf]);
            }
        }
        __syncthreads();
        if (kt + 2 < NKC) {
            load_stage(sbase, mb, kt + 2); CPCOMMIT();
        }
    }

    // ================= fused gate epilogue =================
    float* s_ss = (float*)(smem + HDR_OFF);          // 128 floats (norms -> inv)
    float* s_sc = (float*)(smem + HDR_OFF + 512);    // 8 warps x 64 scores
    float* ls   = (float*)smem;                      // [128][66] logits (overlay, later)

    // kick off simn^T bf16 tile loads (64 KB)
    #pragma unroll
    for (int i = 0; i < 8; ++i) {
        int idx = tid + i * 256;
        CP16(sb0 + SN_HI_OFF + idx * 16, (const void*)(g_snhi + idx));
        CP16(sb0 + SN_LO_OFF + idx * 16, (const void*)(g_snlo + idx));
    }
    CPCOMMIT();

    if (tid < 128) s_ss[tid] = 0.f;
    __syncthreads();

    // bias for this lane's 16 columns
    float2 bv[8];
    #pragma unroll
    for (int nf = 0; nf < 8; ++nf)
        bv[nf] = __ldg((const float2*)(bias + wn * 64 + nf * 8) + (lane & 3));

    // row sumsq from accumulators: quad-reduce, then cross-warp atomicAdd
    #pragma unroll
    for (int mf = 0; mf < 4; ++mf) {
        #pragma unroll
        for (int h2 = 0; h2 < 2; ++h2) {
            float p = 0.f;
            #pragma unroll
            for (int nf = 0; nf < 8; ++nf) {
                float a0 = acc[mf][nf][h2*2]   + bv[nf].x;
                float a1 = acc[mf][nf][h2*2+1] + bv[nf].y;
                p += a0 * a0 + a1 * a1;
            }
            p += __shfl_xor_sync(0xffffffffu, p, 1);
            p += __shfl_xor_sync(0xffffffffu, p, 2);
            if ((lane & 3) == 0)
                atomicAdd(&s_ss[wm * 64 + mf * 16 + (lane >> 2) + h2 * 8], p);
        }
    }
    __syncthreads();
    if (tid < 128) s_ss[tid] = 1.0f / fmaxf(sqrtf(s_ss[tid]), 1e-12f);
    __syncthreads();

    // normalize + bf16 hi/lo split into ldmatrix-ready swizzled smem
    #pragma unroll
    for (int mf = 0; mf < 4; ++mf) {
        #pragma unroll
        for (int h2 = 0; h2 < 2; ++h2) {
            const int r = wm * 64 + mf * 16 + (lane >> 2) + h2 * 8;
            const float fi = s_ss[r];
            #pragma unroll
            for (int nf = 0; nf < 8; ++nf) {
                float v0 = (acc[mf][nf][h2*2]   + bv[nf].x) * fi;
                float v1 = (acc[mf][nf][h2*2+1] + bv[nf].y) * fi;
                __nv_bfloat16 h0 = __float2bfloat16(v0);
                __nv_bfloat16 h1 = __float2bfloat16(v1);
                __nv_bfloat16 l0 = __float2bfloat16(v0 - __bfloat162float(h0));
                __nv_bfloat16 l1 = __float2bfloat16(v1 - __bfloat162float(h1));
                uint32_t hp = (uint32_t)*(uint16_t*)&h0 | ((uint32_t)*(uint16_t*)&h1 << 16);
                uint32_t lp = (uint32_t)*(uint16_t*)&l0 | ((uint32_t)*(uint16_t*)&l1 << 16);
                const uint32_t c6 = (uint32_t)(nf * 8 + (lane & 3) * 2);
                const uint32_t off = (uint32_t)wn * 16384 + sw128((uint32_t)r * 128 + c6 * 2);
                asm volatile("st.shared.b32 [%0], %1;" :: "r"(sb0 + HBF_HI_OFF + off), "r"(hp) : "memory");
                asm volatile("st.shared.b32 [%0], %1;" :: "r"(sb0 + HBF_LO_OFF + off), "r"(lp) : "memory");
            }
        }
    }
    CPWAIT0();
    __syncthreads();

    // gate MMA: warp w -> tokens w*16..w*16+15, all 64 experts, k=256
    const uint32_t aRowG = (uint32_t)(wid * 16 + rA) * 128;
    uint32_t bRowG[4];
    #pragma unroll
    for (int nf2 = 0; nf2 < 4; ++nf2)
        bRowG[nf2] = (uint32_t)(nf2 * 16 + ((lane >> 4) & 1) * 8 + (lane & 7)) * 128;

    float acc2[8][4];
    #pragma unroll
    for (int nf = 0; nf < 8; ++nf)
        #pragma unroll
        for (int i = 0; i < 4; ++i) acc2[nf][i] = 0.f;

    for (int kc = 0; kc < 4; ++kc) {
        const uint32_t aCH = sb0 + HBF_HI_OFF + kc * 16384 + aRowG;
        const uint32_t aCL = sb0 + HBF_LO_OFF + kc * 16384 + aRowG;
        const uint32_t bCH = sb0 + SN_HI_OFF + kc * 8192;
        const uint32_t bCL = sb0 + SN_LO_OFF + kc * 8192;
        #pragma unroll
        for (int ks = 0; ks < 4; ++ks) {
            const uint32_t kb = (uint32_t)ks * 32;
            const uint32_t aOff = (kb + aHalf) ^ xorA;
            const uint32_t bOff = (kb + bHalf) ^ xorB;
            uint32_t aH[4], bH[8][2];
            LDSM4(aH, aCH + aOff);
            #pragma unroll
            for (int nf2 = 0; nf2 < 4; ++nf2) {
                uint32_t r[4];
                LDSM4(r, bCH + bRowG[nf2] + bOff);
                bH[2*nf2][0] = r[0]; bH[2*nf2][1] = r[1];
                bH[2*nf2+1][0] = r[2]; bH[2*nf2+1][1] = r[3];
            }
            #pragma unroll
            for (int nf = 0; nf < 8; ++nf) MMA16816(acc2[nf], aH, bH[nf]);
            {
                uint32_t bL[8][2];
                #pragma unroll
                for (int nf2 = 0; nf2 < 4; ++nf2) {
                    uint32_t r[4];
                    LDSM4(r, bCL + bRowG[nf2] + bOff);
                    bL[2*nf2][0] = r[0]; bL[2*nf2][1] = r[1];
                    bL[2*nf2+1][0] = r[2]; bL[2*nf2+1][1] = r[3];
                }
                #pragma unroll
                for (int nf = 0; nf < 8; ++nf) MMA16816(acc2[nf], aH, bL[nf]);
            }
            {
                uint32_t aL[4];
                LDSM4(aL, aCL + aOff);
                #pragma unroll
                for (int nf = 0; nf < 8; ++nf) MMA16816(acc2[nf], aL, bH[nf]);
            }
        }
    }
    __syncthreads();   // all hbf/snbf reads done before ls overlay

    // scale, mask, write logits to gmem + smem
    const float sc = g_scale;
    const int lr0 = wid * 16 + (lane >> 2);
    #pragma unroll
    for (int nf = 0; nf < 8; ++nf) {
        const int c = nf * 8 + (lane & 3) * 2;
        const float mv0 = __ldg(mask + c), mv1 = __ldg(mask + c + 1);
        float l00 = (mv0 == 0.f) ? -1e9f : acc2[nf][0] * sc;
        float l01 = (mv1 == 0.f) ? -1e9f : acc2[nf][1] * sc;
        float l10 = (mv0 == 0.f) ? -1e9f : acc2[nf][2] * sc;
        float l11 = (mv1 == 0.f) ? -1e9f : acc2[nf][3] * sc;
        *(float2*)(out_logits + (size_t)(mb * BM + lr0) * NEXP + c)     = make_float2(l00, l01);
        *(float2*)(out_logits + (size_t)(mb * BM + lr0 + 8) * NEXP + c) = make_float2(l10, l11);
        *(float2*)&ls[lr0 * 66 + c]       = make_float2(l00, l01);
        *(float2*)&ls[(lr0 + 8) * 66 + c] = make_float2(l10, l11);
    }
    __syncthreads();

    // softmax + sort-free exact top-k (warp per token, 16 tokens/warp)
    const float m0 = __ldg(mask + 2 * lane), m1 = __ldg(mask + 2 * lane + 1);
    float msum = m0 + m1;
    #pragma unroll
    for (int off = 16; off; off >>= 1)
        msum += __shfl_xor_sync(0xffffffffu, msum, off);
    const int active = (int)rintf(msum);
    float* sw = s_sc + wid * 64;
    const int e0 = 2 * lane, e1 = 2 * lane + 1;

    if (out_topk) {
        for (int t = 0; t < 16; ++t) {
            const int lr = wid * 16 + t;
            float2 lv = *(float2*)&ls[lr * 66 + e0];
            float mx = fmaxf(lv.x, lv.y);
            #pragma unroll
            for (int off = 16; off; off >>= 1)
                mx = fmaxf(mx, __shfl_xor_sync(0xffffffffu, mx, off));
            float x0 = expf(lv.x - mx), x1 = expf(lv.y - mx);
            float sum = x0 + x1;
            #pragma unroll
            for (int off = 16; off; off >>= 1)
                sum += __shfl_xor_sync(0xffffffffu, sum, off);
            const float inv_sum = 1.0f / sum;
            const float sA = x0 * inv_sum + 1e-14f;
            const float sB = x1 * inv_sum + 1e-14f;
            sw[e0] = sA; sw[e1] = sB;
            __syncwarp();
            float G0 = 0.f, G1 = 0.f;
            #pragma unroll
            for (int j = 0; j < NEXP; ++j) {
                float sj = sw[j];
                if ((sj > sA) || (sj == sA && j < e0)) G0 += sj;
                if ((sj > sB) || (sj == sB && j < e1)) G1 += sj;
            }
            int cnt = (G0 < 1.0f ? 1 : 0) + (G1 < 1.0f ? 1 : 0);
            #pragma unroll
            for (int off = 16; off; off >>= 1)
                cnt += __shfl_xor_sync(0xffffffffu, cnt, off);
            if (lane == 0)
                out_topk[mb * BM + lr] = (float)min(cnt, active);
            __syncwarp();
        }
    }
}

// ============================================================
extern "C" void kernel_launch(void* const* d_in, const int* in_sizes, int n_in,
                              void* d_out, int out_size)
{
    const float* x    = (const float*)d_in[0];
    const float* W    = (const float*)d_in[1];
    const float* b    = (const float*)d_in[2];
    const float* sim  = (const float*)d_in[3];
    const float* temp = (const float*)d_in[4];
    const float* mask = (const float*)d_in[5];

    float* out = (float*)d_out;
    float* out_topk = (out_size >= N_TOK * NEXP + N_TOK)
                          ? out + (size_t)N_TOK * NEXP : nullptr;

    static int smem_set = 0;
    if (!smem_set) {
        cudaFuncSetAttribute(gemm_gate_kernel,
                             cudaFuncAttributeMaxDynamicSharedMemorySize, SMEM_TOTAL);
        smem_set = 1;
    }

    prep_sim_kernel<<<1, 1024>>>(sim, temp);
    convert_w_kernel<<<NKC, 256>>>(W);
    convert_x_kernel<<<dim3(NMB, NKC), 256>>>(x);
    gemm_gate_kernel<<<NMB, 256, SMEM_TOTAL>>>(b, mask, out, out_topk);
}

// round 5
// speedup vs baseline: 2.0631x; 1.0140x over previous
#include <cuda_runtime.h>
#include <cuda_bf16.h>
#include <math.h>
#include <stdint.h>

#define N_TOK 16384
#define MDIM  2048
#define PDIM  256
#define NEXP  64

#define BM   128
#define BN   256
#define BK   64
#define NKC  (MDIM/BK)     // 32
#define NMB  (N_TOK/BM)    // 128

#define A_TILE_B  (BM*BK*2)        // 16384 B (one of hi/lo)
#define B_TILE_B  (BN*BK*2)        // 32768 B
#define STAGE_B   (2*A_TILE_B + 2*B_TILE_B)   // 98304
// stage-internal offsets
#define SA_HI 0
#define SA_LO A_TILE_B
#define SB_HI (2*A_TILE_B)
#define SB_LO (2*A_TILE_B + B_TILE_B)
// epilogue overlay (within the 2*STAGE_B = 196608 arena)
#define HBF_HI_OFF 0         // [4 kc][128 rows][128B]
#define HBF_LO_OFF 65536
#define SN_HI_OFF  131072    // [4 kc][64 rows][128B]
#define SN_LO_OFF  163840
#define HDR_OFF    196608
#define SMEM_TOTAL (196608 + 512 + 4096)   // 201216

// ---- static device scratch ----
__device__ uint4 g_whi[(size_t)PDIM*MDIM*2/16];    // 1 MB swizzled bf16 hi
__device__ uint4 g_wlo[(size_t)PDIM*MDIM*2/16];    // 1 MB
__device__ uint4 g_snhi[2048];                     // 32 KB simn^T hi
__device__ uint4 g_snlo[2048];                     // 32 KB
__device__ float g_scale;

// ============================================================
static __device__ __forceinline__ uint32_t smem_u32(const void* p) {
    uint32_t a;
    asm("{ .reg .u64 t; cvta.to.shared.u64 t, %1; cvt.u32.u64 %0, t; }"
        : "=r"(a) : "l"(p));
    return a;
}
#define CP16(dst, src) \
    asm volatile("cp.async.cg.shared.global [%0], [%1], 16;" :: "r"(dst), "l"(src))
#define CPCOMMIT() asm volatile("cp.async.commit_group;" ::: "memory")
#define CPWAIT1()  asm volatile("cp.async.wait_group 1;"  ::: "memory")
#define CPWAIT0()  asm volatile("cp.async.wait_group 0;"  ::: "memory")
#define STS32(addr, v) \
    asm volatile("st.shared.b32 [%0], %1;" :: "r"(addr), "r"(v) : "memory")
#define LDSM4(r, addr) \
    asm volatile("ldmatrix.sync.aligned.m8n8.x4.shared.b16 {%0,%1,%2,%3}, [%4];" \
        : "=r"((r)[0]), "=r"((r)[1]), "=r"((r)[2]), "=r"((r)[3]) : "r"(addr))
#define MMA16816(d, a, b) \
    asm volatile("mma.sync.aligned.m16n8k16.row.col.f32.bf16.bf16.f32 " \
        "{%0,%1,%2,%3}, {%4,%5,%6,%7}, {%8,%9}, {%0,%1,%2,%3};" \
        : "+f"((d)[0]), "+f"((d)[1]), "+f"((d)[2]), "+f"((d)[3]) \
        : "r"((a)[0]), "r"((a)[1]), "r"((a)[2]), "r"((a)[3]), \
          "r"((b)[0]), "r"((b)[1]))

static __device__ __forceinline__ uint32_t sw128(uint32_t o) {
    return o ^ ((o >> 3) & 0x70);
}
static __device__ __forceinline__ void split_pack(float f0, float f1,
                                                  uint32_t& hp, uint32_t& lp) {
    __nv_bfloat162 h = __floats2bfloat162_rn(f0, f1);
    float r0 = f0 - __bfloat162float(h.x);
    float r1 = f1 - __bfloat162float(h.y);
    __nv_bfloat162 l = __floats2bfloat162_rn(r0, r1);
    hp = *(uint32_t*)&h;
    lp = *(uint32_t*)&l;
}

// ============================================================
// prep_sim
// ============================================================
__global__ void prep_sim_kernel(const float* __restrict__ sim,
                                const float* __restrict__ temp)
{
    __shared__ float inv[NEXP];
    int t = threadIdx.x;
    if (t < NEXP) {
        float ss = 0.f;
        #pragma unroll 8
        for (int p = 0; p < PDIM; ++p) {
            float v = sim[p * NEXP + t];
            ss += v * v;
        }
        inv[t] = 1.0f / fmaxf(sqrtf(ss), 1e-12f);
    }
    if (t == 0) g_scale = expf(fminf(temp[0], 4.605170185988091f));
    __syncthreads();
    __nv_bfloat16* sh = (__nv_bfloat16*)g_snhi;
    __nv_bfloat16* sl = (__nv_bfloat16*)g_snlo;
    for (int idx = t; idx < NEXP * PDIM; idx += 1024) {
        int e = idx >> 8, p = idx & 255;
        float v = sim[p * NEXP + e] * inv[e];
        __nv_bfloat16 h = __float2bfloat16(v);
        __nv_bfloat16 l = __float2bfloat16(v - __bfloat162float(h));
        uint32_t off = (uint32_t)(p >> 6) * 8192 + sw128((uint32_t)e * 128 + (p & 63) * 2);
        *(__nv_bfloat16*)((char*)sh + off) = h;
        *(__nv_bfloat16*)((char*)sl + off) = l;
    }
}

// ============================================================
// convert_w: W -> swizzled bf16 hi/lo tiles [kc][256 rows][64k]
// ============================================================
__global__ __launch_bounds__(256) void convert_w_kernel(const float* __restrict__ W)
{
    const int kc = blockIdx.x, t = threadIdx.x;
    uint4* dh = g_whi + (size_t)kc * (B_TILE_B / 16);
    uint4* dl = g_wlo + (size_t)kc * (B_TILE_B / 16);
    #pragma unroll
    for (int u = t; u < PDIM * 8; u += 256) {
        int row = u >> 3, cu = u & 7;
        const float* src = W + (size_t)row * MDIM + kc * BK + cu * 8;
        float4 v0 = *(const float4*)(src);
        float4 v1 = *(const float4*)(src + 4);
        uint32_t h0, l0, h1, l1, h2, l2, h3, l3;
        split_pack(v0.x, v0.y, h0, l0);
        split_pack(v0.z, v0.w, h1, l1);
        split_pack(v1.x, v1.y, h2, l2);
        split_pack(v1.z, v1.w, h3, l3);
        uint32_t sw = sw128((uint32_t)row * 128 + cu * 16);
        *(uint4*)((unsigned char*)dh + sw) = make_uint4(h0, h1, h2, h3);
        *(uint4*)((unsigned char*)dl + sw) = make_uint4(l0, l1, l2, l3);
    }
}

// ============================================================
// Fused GEMM + gate
// CTA 128x256x64, 512 thr (16 warps: 4M x 4N), warp tile 32x64
// A loaded fp32 from x, converted in-kernel; B via cp.async
// ============================================================
static __device__ __forceinline__ void sts_a(uint32_t sbase, int arow, int akseg,
                                             const float4* av)
{
    const uint32_t rb = (uint32_t)arow * 128 + (uint32_t)akseg * 2;
    #pragma unroll
    for (int j = 0; j < 4; ++j) {
        uint32_t hp0, lp0, hp1, lp1;
        split_pack(av[j].x, av[j].y, hp0, lp0);
        split_pack(av[j].z, av[j].w, hp1, lp1);
        uint32_t o0 = sw128(rb + j * 8);
        uint32_t o1 = sw128(rb + j * 8 + 4);
        STS32(sbase + SA_HI + o0, hp0);
        STS32(sbase + SA_HI + o1, hp1);
        STS32(sbase + SA_LO + o0, lp0);
        STS32(sbase + SA_LO + o1, lp1);
    }
}

static __device__ __forceinline__ void cp_b(uint32_t sbase, int kt)
{
    const int t = threadIdx.x;
    const uint4* bh = g_whi + (size_t)kt * (B_TILE_B / 16);
    const uint4* bl = g_wlo + (size_t)kt * (B_TILE_B / 16);
    #pragma unroll
    for (int i = 0; i < 4; ++i) {
        int idx = t + i * 512;
        CP16(sbase + SB_HI + idx * 16, (const void*)(bh + idx));
        CP16(sbase + SB_LO + idx * 16, (const void*)(bl + idx));
    }
}

__global__ __launch_bounds__(512, 1) void gemm_gate_kernel(
    const float* __restrict__ x,
    const float* __restrict__ bias,
    const float* __restrict__ mask,
    float* __restrict__ out_logits,
    float* __restrict__ out_topk)
{
    extern __shared__ __align__(1024) unsigned char smem[];
    const uint32_t sb0 = smem_u32(smem);
    const int tid = threadIdx.x, wid = tid >> 5, lane = tid & 31;
    const int mb = blockIdx.x;
    const int wm = wid & 3;        // 0..3 (M, 32 rows)
    const int wn = wid >> 2;       // 0..3 (N, 64 cols)

    // A loader mapping: 4 threads per row, 16 contiguous k each
    const int arow  = tid >> 2;
    const int akseg = (tid & 3) * 16;
    const float* aptr = x + (size_t)(mb * BM + arow) * MDIM + akseg;

    float4 av[4];
    // prologue: stage 0
    #pragma unroll
    for (int j = 0; j < 4; ++j) av[j] = *(const float4*)(aptr + j * 4);
    sts_a(sb0, arow, akseg, av);
    cp_b(sb0, 0); CPCOMMIT();
    // stage 1
    #pragma unroll
    for (int j = 0; j < 4; ++j) av[j] = *(const float4*)(aptr + BK + j * 4);
    sts_a(sb0 + STAGE_B, arow, akseg, av);
    cp_b(sb0 + STAGE_B, 1); CPCOMMIT();
    // preload A for stage 2
    #pragma unroll
    for (int j = 0; j < 4; ++j) av[j] = *(const float4*)(aptr + 2 * BK + j * 4);

    const int rA = lane & 15;
    const uint32_t aHalf = (uint32_t)(lane >> 4) * 16;
    const uint32_t xorA = (uint32_t)(rA & 7) << 4;
    uint32_t aRow[2];
    #pragma unroll
    for (int mf = 0; mf < 2; ++mf)
        aRow[mf] = (uint32_t)(wm * 32 + mf * 16 + rA) * 128;

    const uint32_t bHalf = (uint32_t)((lane >> 3) & 1) * 16;
    const uint32_t xorB = (uint32_t)(lane & 7) << 4;
    uint32_t bRow[4];
    #pragma unroll
    for (int nf2 = 0; nf2 < 4; ++nf2)
        bRow[nf2] = (uint32_t)(wn * 64 + nf2 * 16 + ((lane >> 4) & 1) * 8 + (lane & 7)) * 128;

    float acc[2][8][4];
    #pragma unroll
    for (int mf = 0; mf < 2; ++mf)
        #pragma unroll
        for (int nf = 0; nf < 8; ++nf)
            #pragma unroll
            for (int i = 0; i < 4; ++i) acc[mf][nf][i] = 0.f;

    for (int kt = 0; kt < NKC; ++kt) {
        const uint32_t sbase = sb0 + (kt & 1) * STAGE_B;
        if (kt == NKC - 1) { CPWAIT0(); } else { CPWAIT1(); }
        __syncthreads();

        #pragma unroll
        for (int ks = 0; ks < 4; ++ks) {
            const uint32_t kb = (uint32_t)ks * 32;
            const uint32_t aOff = (kb + aHalf) ^ xorA;
            const uint32_t bOff = (kb + bHalf) ^ xorB;

            uint32_t aH[2][4], aL[2][4], bfr[8][2];
            #pragma unroll
            for (int mf = 0; mf < 2; ++mf)
                LDSM4(aH[mf], sbase + SA_HI + aRow[mf] + aOff);
            #pragma unroll
            for (int nf2 = 0; nf2 < 4; ++nf2) {
                uint32_t r[4];
                LDSM4(r, sbase + SB_HI + bRow[nf2] + bOff);
                bfr[2*nf2][0] = r[0]; bfr[2*nf2][1] = r[1];
                bfr[2*nf2+1][0] = r[2]; bfr[2*nf2+1][1] = r[3];
            }
            #pragma unroll
            for (int mf = 0; mf < 2; ++mf)
                #pragma unroll
                for (int nf = 0; nf < 8; ++nf)
                    MMA16816(acc[mf][nf], aH[mf], bfr[nf]);
            #pragma unroll
            for (int mf = 0; mf < 2; ++mf)
                LDSM4(aL[mf], sbase + SA_LO + aRow[mf] + aOff);
            #pragma unroll
            for (int mf = 0; mf < 2; ++mf)
                #pragma unroll
                for (int nf = 0; nf < 8; ++nf)
                    MMA16816(acc[mf][nf], aL[mf], bfr[nf]);
            #pragma unroll
            for (int nf2 = 0; nf2 < 4; ++nf2) {
                uint32_t r[4];
                LDSM4(r, sbase + SB_LO + bRow[nf2] + bOff);
                bfr[2*nf2][0] = r[0]; bfr[2*nf2][1] = r[1];
                bfr[2*nf2+1][0] = r[2]; bfr[2*nf2+1][1] = r[3];
            }
            #pragma unroll
            for (int mf = 0; mf < 2; ++mf)
                #pragma unroll
                for (int nf = 0; nf < 8; ++nf)
                    MMA16816(acc[mf][nf], aH[mf], bfr[nf]);
        }
        __syncthreads();
        if (kt + 2 < NKC) {
            sts_a(sbase, arow, akseg, av);
            cp_b(sbase, kt + 2); CPCOMMIT();
            if (kt + 3 < NKC) {
                #pragma unroll
                for (int j = 0; j < 4; ++j)
                    av[j] = *(const float4*)(aptr + (kt + 3) * BK + j * 4);
            }
        }
    }

    // ================= fused gate epilogue =================
    float* s_ss = (float*)(smem + HDR_OFF);          // 128 norms
    float* s_sc = (float*)(smem + HDR_OFF + 512);    // 16 warps x 64 scores
    float* ls   = (float*)smem;                      // [128][66] logits overlay

    // load simn^T tiles (64 KB)
    #pragma unroll
    for (int i = 0; i < 4; ++i) {
        int idx = tid + i * 512;
        CP16(sb0 + SN_HI_OFF + idx * 16, (const void*)(g_snhi + idx));
        CP16(sb0 + SN_LO_OFF + idx * 16, (const void*)(g_snlo + idx));
    }
    CPCOMMIT();

    if (tid < 128) s_ss[tid] = 0.f;
    __syncthreads();

    float2 bv[8];
    #pragma unroll
    for (int nf = 0; nf < 8; ++nf)
        bv[nf] = __ldg((const float2*)(bias + wn * 64 + nf * 8) + (lane & 3));

    #pragma unroll
    for (int mf = 0; mf < 2; ++mf) {
        #pragma unroll
        for (int h2 = 0; h2 < 2; ++h2) {
            float p = 0.f;
            #pragma unroll
            for (int nf = 0; nf < 8; ++nf) {
                float a0 = acc[mf][nf][h2*2]   + bv[nf].x;
                float a1 = acc[mf][nf][h2*2+1] + bv[nf].y;
                p += a0 * a0 + a1 * a1;
            }
            p += __shfl_xor_sync(0xffffffffu, p, 1);
            p += __shfl_xor_sync(0xffffffffu, p, 2);
            if ((lane & 3) == 0)
                atomicAdd(&s_ss[wm * 32 + mf * 16 + (lane >> 2) + h2 * 8], p);
        }
    }
    __syncthreads();
    if (tid < 128) s_ss[tid] = 1.0f / fmaxf(sqrtf(s_ss[tid]), 1e-12f);
    __syncthreads();

    // normalize + bf16 hi/lo into swizzled smem (wn -> kc chunk)
    #pragma unroll
    for (int mf = 0; mf < 2; ++mf) {
        #pragma unroll
        for (int h2 = 0; h2 < 2; ++h2) {
            const int r = wm * 32 + mf * 16 + (lane >> 2) + h2 * 8;
            const float fi = s_ss[r];
            #pragma unroll
            for (int nf = 0; nf < 8; ++nf) {
                float v0 = (acc[mf][nf][h2*2]   + bv[nf].x) * fi;
                float v1 = (acc[mf][nf][h2*2+1] + bv[nf].y) * fi;
                uint32_t hp, lp;
                split_pack(v0, v1, hp, lp);
                const uint32_t c6 = (uint32_t)(nf * 8 + (lane & 3) * 2);
                const uint32_t off = (uint32_t)wn * 16384 + sw128((uint32_t)r * 128 + c6 * 2);
                STS32(sb0 + HBF_HI_OFF + off, hp);
                STS32(sb0 + HBF_LO_OFF + off, lp);
            }
        }
    }
    CPWAIT0();
    __syncthreads();

    // gate MMA: warps 0-7, 16 tokens each, 64 experts, k=256
    if (wid < 8) {
        const uint32_t aRowG = (uint32_t)(wid * 16 + rA) * 128;
        uint32_t bRowG[4];
        #pragma unroll
        for (int nf2 = 0; nf2 < 4; ++nf2)
            bRowG[nf2] = (uint32_t)(nf2 * 16 + ((lane >> 4) & 1) * 8 + (lane & 7)) * 128;

        float acc2[8][4];
        #pragma unroll
        for (int nf = 0; nf < 8; ++nf)
            #pragma unroll
            for (int i = 0; i < 4; ++i) acc2[nf][i] = 0.f;

        #pragma unroll
        for (int kc = 0; kc < 4; ++kc) {
            const uint32_t aCH = sb0 + HBF_HI_OFF + kc * 16384 + aRowG;
            const uint32_t aCL = sb0 + HBF_LO_OFF + kc * 16384 + aRowG;
            const uint32_t bCH = sb0 + SN_HI_OFF + kc * 8192;
            const uint32_t bCL = sb0 + SN_LO_OFF + kc * 8192;
            #pragma unroll
            for (int ks = 0; ks < 4; ++ks) {
                const uint32_t kb = (uint32_t)ks * 32;
                const uint32_t aOff = (kb + aHalf) ^ xorA;
                const uint32_t bOff = (kb + bHalf) ^ xorB;
                uint32_t aH[4], aL[4], bfr[8][2];
                LDSM4(aH, aCH + aOff);
                #pragma unroll
                for (int nf2 = 0; nf2 < 4; ++nf2) {
                    uint32_t r[4];
                    LDSM4(r, bCH + bRowG[nf2] + bOff);
                    bfr[2*nf2][0] = r[0]; bfr[2*nf2][1] = r[1];
                    bfr[2*nf2+1][0] = r[2]; bfr[2*nf2+1][1] = r[3];
                }
                #pragma unroll
                for (int nf = 0; nf < 8; ++nf) MMA16816(acc2[nf], aH, bfr[nf]);
                LDSM4(aL, aCL + aOff);
                #pragma unroll
                for (int nf = 0; nf < 8; ++nf) MMA16816(acc2[nf], aL, bfr[nf]);
                #pragma unroll
                for (int nf2 = 0; nf2 < 4; ++nf2) {
                    uint32_t r[4];
                    LDSM4(r, bCL + bRowG[nf2] + bOff);
                    bfr[2*nf2][0] = r[0]; bfr[2*nf2][1] = r[1];
                    bfr[2*nf2+1][0] = r[2]; bfr[2*nf2+1][1] = r[3];
                }
                #pragma unroll
                for (int nf = 0; nf < 8; ++nf) MMA16816(acc2[nf], aH, bfr[nf]);
            }
        }
        __syncthreads();   // hbf/sn reads done before ls overlay

        // scale, mask, write logits gmem + smem
        const float sc = g_scale;
        const int lr0 = wid * 16 + (lane >> 2);
        #pragma unroll
        for (int nf = 0; nf < 8; ++nf) {
            const int c = nf * 8 + (lane & 3) * 2;
            const float mv0 = __ldg(mask + c), mv1 = __ldg(mask + c + 1);
            float l00 = (mv0 == 0.f) ? -1e9f : acc2[nf][0] * sc;
            float l01 = (mv1 == 0.f) ? -1e9f : acc2[nf][1] * sc;
            float l10 = (mv0 == 0.f) ? -1e9f : acc2[nf][2] * sc;
            float l11 = (mv1 == 0.f) ? -1e9f : acc2[nf][3] * sc;
            *(float2*)(out_logits + (size_t)(mb * BM + lr0) * NEXP + c)     = make_float2(l00, l01);
            *(float2*)(out_logits + (size_t)(mb * BM + lr0 + 8) * NEXP + c) = make_float2(l10, l11);
            *(float2*)&ls[lr0 * 66 + c]       = make_float2(l00, l01);
            *(float2*)&ls[(lr0 + 8) * 66 + c] = make_float2(l10, l11);
        }
    } else {
        __syncthreads();
    }
    __syncthreads();

    // softmax + sort-free exact top-k: 16 warps, 8 tokens each
    const float m0 = __ldg(mask + 2 * lane), m1 = __ldg(mask + 2 * lane + 1);
    float msum = m0 + m1;
    #pragma unroll
    for (int off = 16; off; off >>= 1)
        msum += __shfl_xor_sync(0xffffffffu, msum, off);
    const int active = (int)rintf(msum);
    float* sw = s_sc + wid * 64;
    const int e0 = 2 * lane, e1 = 2 * lane + 1;

    if (out_topk) {
        #pragma unroll 1
        for (int t = 0; t < 8; ++t) {
            const int lr = wid * 8 + t;
            float2 lv = *(float2*)&ls[lr * 66 + e0];
            float mx = fmaxf(lv.x, lv.y);
            #pragma unroll
            for (int off = 16; off; off >>= 1)
                mx = fmaxf(mx, __shfl_xor_sync(0xffffffffu, mx, off));
            float x0 = expf(lv.x - mx), x1 = expf(lv.y - mx);
            float sum = x0 + x1;
            #pragma unroll
            for (int off = 16; off; off >>= 1)
                sum += __shfl_xor_sync(0xffffffffu, sum, off);
            const float inv_sum = 1.0f / sum;
            const float sA = x0 * inv_sum + 1e-14f;
            const float sB = x1 * inv_sum + 1e-14f;
            sw[e0] = sA; sw[e1] = sB;
            __syncwarp();
            float G0 = 0.f, G1 = 0.f;
            #pragma unroll
            for (int j = 0; j < NEXP; ++j) {
                float sj = sw[j];
                if ((sj > sA) || (sj == sA && j < e0)) G0 += sj;
                if ((sj > sB) || (sj == sB && j < e1)) G1 += sj;
            }
            int cnt = (G0 < 1.0f ? 1 : 0) + (G1 < 1.0f ? 1 : 0);
            #pragma unroll
            for (int off = 16; off; off >>= 1)
                cnt += __shfl_xor_sync(0xffffffffu, cnt, off);
            if (lane == 0)
                out_topk[mb * BM + lr] = (float)min(cnt, active);
            __syncwarp();
        }
    }
}

// ============================================================
extern "C" void kernel_launch(void* const* d_in, const int* in_sizes, int n_in,
                              void* d_out, int out_size)
{
    const float* x    = (const float*)d_in[0];
    const float* W    = (const float*)d_in[1];
    const float* b    = (const float*)d_in[2];
    const float* sim  = (const float*)d_in[3];
    const float* temp = (const float*)d_in[4];
    const float* mask = (const float*)d_in[5];

    float* out = (float*)d_out;
    float* out_topk = (out_size >= N_TOK * NEXP + N_TOK)
                          ? out + (size_t)N_TOK * NEXP : nullptr;

    static int smem_set = 0;
    if (!smem_set) {
        cudaFuncSetAttribute(gemm_gate_kernel,
                             cudaFuncAttributeMaxDynamicSharedMemorySize, SMEM_TOTAL);
        smem_set = 1;
    }

    prep_sim_kernel<<<1, 1024>>>(sim, temp);
    convert_w_kernel<<<NKC, 256>>>(W);
    gemm_gate_kernel<<<NMB, 512, SMEM_TOTAL>>>(x, b, mask, out, out_topk);
}